// round 1
// baseline (speedup 1.0000x reference)
#include <cuda_runtime.h>
#include <math.h>
#include <stdint.h>

#define NN    30000
#define EE    480000
#define HIDN  256
#define NLAY  6

// ---------------- static device scratch (no allocations allowed) ----------------
static __device__ __align__(128) float g_h[2][NN * HIDN];
static __device__ __align__(128) float g_xl[NN * HIDN];
static __device__ __align__(128) float g_xr[NN * HIDN];
static __device__ __align__(128) float g_t[NN * 128];
static __device__ __align__(128) float g_B[NLAY * 10 * 256];   // composed edge->ep matrices
static __device__ __align__(128) float g_c[NLAY * 256];        // composed ep bias
static __device__ __align__(128) float g_A[NLAY * 10 * 256];   // A_i chain
static __device__ __align__(128) float g_d[NLAY * 256];        // d_i chain
static __device__ int g_cnt[NN + 1];
static __device__ int g_start[NN + 1];
static __device__ int g_cursor[NN + 1];
static __device__ int g_eid[EE];

// ---------------- CSR build ----------------
__global__ void zero_kernel() {
    int i = blockIdx.x * 256 + threadIdx.x;
    if (i <= NN) g_cnt[i] = 0;
}

__global__ void count_kernel(const int* __restrict__ dst) {
    int e = blockIdx.x * 256 + threadIdx.x;
    if (e < EE) atomicAdd(&g_cnt[dst[e]], 1);
}

__global__ void scan_kernel() {
    __shared__ int part[1024];
    const int T = 1024;
    const int ITEMS = (NN + T - 1) / T;   // 30
    int tid = threadIdx.x;
    int base = tid * ITEMS;
    int s = 0;
    for (int i = 0; i < ITEMS; ++i) {
        int idx = base + i;
        if (idx < NN) s += g_cnt[idx];
    }
    part[tid] = s;
    __syncthreads();
    for (int off = 1; off < T; off <<= 1) {
        int v = 0;
        if (tid >= off) v = part[tid - off];
        __syncthreads();
        part[tid] += v;
        __syncthreads();
    }
    int run = (tid == 0) ? 0 : part[tid - 1];
    for (int i = 0; i < ITEMS; ++i) {
        int idx = base + i;
        if (idx < NN) {
            g_start[idx] = run;
            g_cursor[idx] = run;
            run += g_cnt[idx];
        }
    }
    if (tid == T - 1) g_start[NN] = part[T - 1];
}

__global__ void fill_kernel(const int* __restrict__ dst) {
    int e = blockIdx.x * 256 + threadIdx.x;
    if (e < EE) {
        int pos = atomicAdd(&g_cursor[dst[e]], 1);
        g_eid[pos] = e;
    }
}

// deterministic order: sort each node's edge list ascending (stable result)
__global__ void sort_kernel() {
    int n = blockIdx.x * 256 + threadIdx.x;
    if (n >= NN) return;
    int s0 = g_start[n], s1 = g_start[n + 1];
    for (int i = s0 + 1; i < s1; ++i) {
        int v = g_eid[i];
        int j = i - 1;
        while (j >= s0 && g_eid[j] > v) { g_eid[j + 1] = g_eid[j]; --j; }
        g_eid[j + 1] = v;
    }
}

// ---------------- edge-matrix chain precompute ----------------
// ea_i = edge_attr @ A_i + d_i;  A_0 = edge_W, d_0 = edge_b
// A_{i+1} = A_i @ Weu_i ; d_{i+1} = d_i @ Weu_i + beu_i
__global__ void chain_kernel(const float* __restrict__ eW, const float* __restrict__ eb,
                             const float* __restrict__ Weu, const float* __restrict__ beu) {
    __shared__ float Ash[10 * 256];
    __shared__ float dsh[256];
    int tid = threadIdx.x;  // 256 threads
    for (int t = tid; t < 2560; t += 256) Ash[t] = eW[t];
    dsh[tid] = eb[tid];
    __syncthreads();
    for (int i = 0; i < NLAY; ++i) {
        for (int t = tid; t < 2560; t += 256) g_A[i * 2560 + t] = Ash[t];
        g_d[i * 256 + tid] = dsh[tid];
        __syncthreads();
        if (i == NLAY - 1) break;
        const float* Wp = Weu + (size_t)i * 65536;
        float accA[10];
        #pragma unroll
        for (int k = 0; k < 10; ++k) accA[k] = 0.f;
        float accd = 0.f;
        for (int c = 0; c < 256; ++c) {
            float w = Wp[c * 256 + tid];
            accd = fmaf(dsh[c], w, accd);
            #pragma unroll
            for (int k = 0; k < 10; ++k) accA[k] = fmaf(Ash[k * 256 + c], w, accA[k]);
        }
        accd += beu[i * 256 + tid];
        __syncthreads();
        #pragma unroll
        for (int k = 0; k < 10; ++k) Ash[k * 256 + tid] = accA[k];
        dsh[tid] = accd;
        __syncthreads();
    }
}

// B_i = A_i @ We_i ; c_i = d_i @ We_i   (6 blocks in parallel)
__global__ void bmat_kernel(const float* __restrict__ We) {
    __shared__ float Ash[10 * 256];
    __shared__ float dsh[256];
    int i = blockIdx.x;
    int tid = threadIdx.x;
    for (int t = tid; t < 2560; t += 256) Ash[t] = g_A[i * 2560 + t];
    dsh[tid] = g_d[i * 256 + tid];
    __syncthreads();
    const float* Wp = We + (size_t)i * 65536;
    float accB[10];
    #pragma unroll
    for (int k = 0; k < 10; ++k) accB[k] = 0.f;
    float accc = 0.f;
    for (int c = 0; c < 256; ++c) {
        float w = Wp[c * 256 + tid];
        accc = fmaf(dsh[c], w, accc);
        #pragma unroll
        for (int k = 0; k < 10; ++k) accB[k] = fmaf(Ash[k * 256 + c], w, accB[k]);
    }
    #pragma unroll
    for (int k = 0; k < 10; ++k) g_B[i * 2560 + k * 256 + tid] = accB[k];
    g_c[i * 256 + tid] = accc;
}

// ---------------- node encoder: h0 = x @ node_W + node_b ----------------
__global__ void encoder_kernel(const float* __restrict__ x, const float* __restrict__ nW,
                               const float* __restrict__ nb) {
    int idx = blockIdx.x * 256 + threadIdx.x;
    int n = idx >> 8, c = idx & 255;
    if (n >= NN) return;
    float s = nb[c];
    #pragma unroll
    for (int k = 0; k < 13; ++k) s = fmaf(x[n * 13 + k], nW[k * 256 + c], s);
    g_h[0][idx] = s;
}

// ---------------- fp32 tiled GEMM: C = h[hsel] @ W + bias, optional leaky ----------------
// BM=128 BN=64 BK=16, 256 threads, 8x4 per thread.
// Column blocks [0,N0) take (W0,b0)->C0, [N0,..) take (W1,b1)->g_xr.
__global__ void gemm_kernel(int hsel,
                            const float* __restrict__ W0, const float* __restrict__ b0,
                            const float* __restrict__ W1, const float* __restrict__ b1,
                            int N0, int Wld, int mode, int ldc, float slope) {
    __shared__ __align__(16) float As[16][129];
    __shared__ __align__(16) float Bs[16][64];
    const float* __restrict__ A = g_h[hsel];
    const int M = NN, K = HIDN;
    int tid = threadIdx.x;
    int tx = tid & 15, ty = tid >> 4;
    int m0 = blockIdx.x * 128;
    int colg = blockIdx.y * 64;
    const float* W; const float* bias; float* C; int wc0;
    if (colg < N0) { W = W0; bias = b0; C = (mode == 0) ? g_xl : g_t; wc0 = colg; }
    else           { W = W1; bias = b1; C = g_xr;                     wc0 = colg - N0; }

    float acc[8][4];
    #pragma unroll
    for (int r = 0; r < 8; ++r)
        #pragma unroll
        for (int c = 0; c < 4; ++c) acc[r][c] = 0.f;

    int arow = tid >> 2;
    int ac = (tid & 3) << 2;
    int brow = tid >> 4;
    int bc = tx << 2;

    for (int kk = 0; kk < K; kk += 16) {
        #pragma unroll
        for (int half = 0; half < 2; ++half) {
            int r = arow + half * 64;
            int gm = m0 + r;
            float4 av = make_float4(0.f, 0.f, 0.f, 0.f);
            if (gm < M) av = *(const float4*)(A + (size_t)gm * K + kk + ac);
            As[ac + 0][r] = av.x; As[ac + 1][r] = av.y;
            As[ac + 2][r] = av.z; As[ac + 3][r] = av.w;
        }
        float4 bv = *(const float4*)(W + (size_t)(kk + brow) * Wld + wc0 + bc);
        *(float4*)&Bs[brow][bc] = bv;
        __syncthreads();
        #pragma unroll
        for (int k = 0; k < 16; ++k) {
            float a[8], b[4];
            #pragma unroll
            for (int r = 0; r < 8; ++r) a[r] = As[k][ty * 8 + r];
            #pragma unroll
            for (int c = 0; c < 4; ++c) b[c] = Bs[k][bc + c];
            #pragma unroll
            for (int r = 0; r < 8; ++r)
                #pragma unroll
                for (int c = 0; c < 4; ++c) acc[r][c] = fmaf(a[r], b[c], acc[r][c]);
        }
        __syncthreads();
    }

    #pragma unroll
    for (int r = 0; r < 8; ++r) {
        int gm = m0 + ty * 8 + r;
        if (gm < M) {
            float4 o;
            float v;
            v = acc[r][0] + bias[wc0 + bc + 0]; o.x = v >= 0.f ? v : slope * v;
            v = acc[r][1] + bias[wc0 + bc + 1]; o.y = v >= 0.f ? v : slope * v;
            v = acc[r][2] + bias[wc0 + bc + 2]; o.z = v >= 0.f ? v : slope * v;
            v = acc[r][3] + bias[wc0 + bc + 3]; o.w = v >= 0.f ? v : slope * v;
            *(float4*)(C + (size_t)gm * ldc + wc0 + bc) = o;
        }
    }
}

// ---------------- fused GATv2 attention + BN + leaky + residual ----------------
// one warp per destination node; lane owns channel h*32+lane for each head h.
__global__ void attn_kernel(int layer, int hin,
                            const float* __restrict__ att, const float* __restrict__ conv_b,
                            const float* __restrict__ bng, const float* __restrict__ bnb,
                            const float* __restrict__ bnrm, const float* __restrict__ bnrv,
                            const int* __restrict__ src_arr,
                            const float* __restrict__ eattr) {
    __shared__ float Bsh[2560];
    __shared__ float csh[256];
    __shared__ float attsh[256];
    __shared__ float cbsh[256];
    __shared__ float scsh[256];
    __shared__ float shsh[256];
    int tid = threadIdx.x;
    for (int t = tid; t < 2560; t += 256) Bsh[t] = g_B[layer * 2560 + t];
    {
        int c = tid;
        csh[c]   = g_c[layer * 256 + c];
        attsh[c] = att[layer * 256 + c];
        cbsh[c]  = conv_b[layer * 256 + c];
        float sc = bng[layer * 256 + c] * rsqrtf(bnrv[layer * 256 + c] + 1e-5f);
        scsh[c]  = sc;
        shsh[c]  = bnb[layer * 256 + c] - bnrm[layer * 256 + c] * sc;
    }
    __syncthreads();

    int warp = tid >> 5, lane = tid & 31;
    int n = blockIdx.x * 8 + warp;
    if (n >= NN) return;
    int hout = hin ^ 1;

    float xr8[8], mh[8], ssum[8], accv[8];
    #pragma unroll
    for (int h = 0; h < 8; ++h) {
        xr8[h] = g_xr[n * 256 + h * 32 + lane];
        mh[h] = -INFINITY; ssum[h] = 0.f; accv[h] = 0.f;
    }

    int s0 = g_start[n], s1 = g_start[n + 1];
    for (int p = s0; p < s1; ++p) {
        int e = g_eid[p];
        int sn = src_arr[e];
        float eav = (lane < 10) ? eattr[e * 10 + lane] : 0.f;
        float xls[8], val[8];
        #pragma unroll
        for (int h = 0; h < 8; ++h) {
            xls[h] = g_xl[sn * 256 + h * 32 + lane];
            val[h] = csh[h * 32 + lane];
        }
        #pragma unroll
        for (int k = 0; k < 10; ++k) {
            float a = __shfl_sync(0xffffffffu, eav, k);
            #pragma unroll
            for (int h = 0; h < 8; ++h)
                val[h] = fmaf(a, Bsh[k * 256 + h * 32 + lane], val[h]);
        }
        #pragma unroll
        for (int h = 0; h < 8; ++h) {
            float v = xls[h] + xr8[h] + val[h];
            v = v >= 0.f ? v : 0.2f * v;         // leaky 0.2
            val[h] = v * attsh[h * 32 + lane];
        }
        #pragma unroll
        for (int off = 16; off > 0; off >>= 1) {
            #pragma unroll
            for (int h = 0; h < 8; ++h)
                val[h] += __shfl_xor_sync(0xffffffffu, val[h], off);
        }
        #pragma unroll
        for (int h = 0; h < 8; ++h) {
            float L = val[h];
            float nm = fmaxf(mh[h], L);
            float f = __expf(mh[h] - nm);
            float w = __expf(L - nm);
            ssum[h] = ssum[h] * f + w;
            accv[h] = accv[h] * f + w * xls[h];
            mh[h] = nm;
        }
    }

    #pragma unroll
    for (int h = 0; h < 8; ++h) {
        int c = h * 32 + lane;
        float agg = accv[h] / (ssum[h] + 1e-16f);
        float v = agg + cbsh[c];
        v = v * scsh[c] + shsh[c];               // BN (eval)
        v = v >= 0.f ? v : 0.01f * v;            // leaky 0.01
        if (layer >= 1) v += g_h[hin][n * 256 + c];  // residual
        g_h[hout][n * 256 + c] = v;
    }
}

// ---------------- head: out = t @ W2 + b2 ----------------
__global__ void head2_kernel(const float* __restrict__ W2, const float* __restrict__ b2,
                             float* __restrict__ out) {
    __shared__ float w[128];
    int tid = threadIdx.x;
    if (tid < 128) w[tid] = W2[tid];
    __syncthreads();
    int n = blockIdx.x * 256 + tid;
    if (n >= NN) return;
    float s = b2[0];
    const float* tp = g_t + (size_t)n * 128;
    #pragma unroll
    for (int j = 0; j < 128; ++j) s = fmaf(tp[j], w[j], s);
    out[n] = s;
}

// ---------------- launch ----------------
extern "C" void kernel_launch(void* const* d_in, const int* in_sizes, int n_in,
                              void* d_out, int out_size) {
    const float* x      = (const float*)d_in[0];
    const int*   ei     = (const int*)d_in[1];
    const float* eattr  = (const float*)d_in[2];
    const float* nW     = (const float*)d_in[3];
    const float* nb     = (const float*)d_in[4];
    const float* eW     = (const float*)d_in[5];
    const float* eb     = (const float*)d_in[6];
    const float* Wl     = (const float*)d_in[7];
    const float* bl     = (const float*)d_in[8];
    const float* Wr     = (const float*)d_in[9];
    const float* br     = (const float*)d_in[10];
    const float* We     = (const float*)d_in[11];
    const float* att    = (const float*)d_in[12];
    const float* conv_b = (const float*)d_in[13];
    const float* Weu    = (const float*)d_in[14];
    const float* beu    = (const float*)d_in[15];
    const float* bng    = (const float*)d_in[16];
    const float* bnb    = (const float*)d_in[17];
    const float* bnrm   = (const float*)d_in[18];
    const float* bnrv   = (const float*)d_in[19];
    const float* oW1    = (const float*)d_in[20];
    const float* ob1    = (const float*)d_in[21];
    const float* oW2    = (const float*)d_in[22];
    const float* ob2    = (const float*)d_in[23];

    const int* srcp = ei;
    const int* dstp = ei + EE;

    // CSR build (deterministic)
    zero_kernel<<<(NN + 256) / 256, 256>>>();
    count_kernel<<<(EE + 255) / 256, 256>>>(dstp);
    scan_kernel<<<1, 1024>>>();
    fill_kernel<<<(EE + 255) / 256, 256>>>(dstp);
    sort_kernel<<<(NN + 255) / 256, 256>>>();

    // edge matrix chain: collapses all E x 256 x 256 edge GEMMs
    chain_kernel<<<1, 256>>>(eW, eb, Weu, beu);
    bmat_kernel<<<NLAY, 256>>>(We);

    // node encoder
    encoder_kernel<<<NN, 256>>>(x, nW, nb);

    dim3 gemm_grid((NN + 127) / 128, 8);
    dim3 head_grid((NN + 127) / 128, 2);
    int cur = 0;
    for (int i = 0; i < NLAY; ++i) {
        gemm_kernel<<<gemm_grid, 256>>>(cur,
            Wl + (size_t)i * 65536, bl + i * 256,
            Wr + (size_t)i * 65536, br + i * 256,
            256, 256, /*mode=*/0, /*ldc=*/256, /*slope=*/1.0f);
        attn_kernel<<<(NN + 7) / 8, 256>>>(i, cur, att, conv_b, bng, bnb, bnrm, bnrv,
                                           srcp, eattr);
        cur ^= 1;
    }

    // output head
    gemm_kernel<<<head_grid, 256>>>(cur,
        oW1, ob1, (const float*)0, (const float*)0,
        128, 128, /*mode=*/1, /*ldc=*/128, /*slope=*/0.01f);
    head2_kernel<<<(NN + 255) / 256, 256>>>(oW2, ob2, (float*)d_out);
}